// round 1
// baseline (speedup 1.0000x reference)
#include <cuda_runtime.h>

#define RES 256
#define N_TOTAL (8 * 65536)

__global__ __launch_bounds__(256) void volume_sample_kernel(
    const float* __restrict__ x,
    const float* __restrict__ vol,
    float* __restrict__ out)
{
    int i = blockIdx.x * blockDim.x + threadIdx.x;
    if (i >= N_TOTAL) return;

    // coords (x,y,z) index (W,H,D); EXTENT=0.5 so coord = 2*x_in, and
    // ix = ((coord+1)*256 - 1)/2 = 256*x_in + 127.5
    float gx = x[3 * i + 0];
    float gy = x[3 * i + 1];
    float gz = x[3 * i + 2];

    float ix = fmaf(gx, 256.0f, 127.5f);
    float iy = fmaf(gy, 256.0f, 127.5f);
    float iz = fmaf(gz, 256.0f, 127.5f);

    float fx0 = floorf(ix);
    float fy0 = floorf(iy);
    float fz0 = floorf(iz);

    float tx = ix - fx0;
    float ty = iy - fy0;
    float tz = iz - fz0;

    int x0 = (int)fx0;
    int y0 = (int)fy0;
    int z0 = (int)fz0;
    int x1 = x0 + 1;
    int y1 = y0 + 1;
    int z1 = z0 + 1;

    bool vx0 = (x0 >= 0) & (x0 < RES);
    bool vx1 = (x1 >= 0) & (x1 < RES);
    bool vy0 = (y0 >= 0) & (y0 < RES);
    bool vy1 = (y1 >= 0) & (y1 < RES);
    bool vz0 = (z0 >= 0) & (z0 < RES);
    bool vz1 = (z1 >= 0) & (z1 < RES);

    // clamped indices for safe addressing; invalid corners zeroed via select
    int cx0 = min(max(x0, 0), RES - 1);
    int cx1 = min(max(x1, 0), RES - 1);
    int cy0 = min(max(y0, 0), RES - 1);
    int cy1 = min(max(y1, 0), RES - 1);
    int cz0 = min(max(z0, 0), RES - 1);
    int cz1 = min(max(z1, 0), RES - 1);

    long pz0 = (long)cz0 * (RES * RES);
    long pz1 = (long)cz1 * (RES * RES);
    int  ry0 = cy0 * RES;
    int  ry1 = cy1 * RES;

    // 8 independent gathers (max MLP)
    float v000 = __ldg(vol + pz0 + ry0 + cx0);
    float v001 = __ldg(vol + pz0 + ry0 + cx1);
    float v010 = __ldg(vol + pz0 + ry1 + cx0);
    float v011 = __ldg(vol + pz0 + ry1 + cx1);
    float v100 = __ldg(vol + pz1 + ry0 + cx0);
    float v101 = __ldg(vol + pz1 + ry0 + cx1);
    float v110 = __ldg(vol + pz1 + ry1 + cx0);
    float v111 = __ldg(vol + pz1 + ry1 + cx1);

    v000 = (vz0 & vy0 & vx0) ? v000 : 0.0f;
    v001 = (vz0 & vy0 & vx1) ? v001 : 0.0f;
    v010 = (vz0 & vy1 & vx0) ? v010 : 0.0f;
    v011 = (vz0 & vy1 & vx1) ? v011 : 0.0f;
    v100 = (vz1 & vy0 & vx0) ? v100 : 0.0f;
    v101 = (vz1 & vy0 & vx1) ? v101 : 0.0f;
    v110 = (vz1 & vy1 & vx0) ? v110 : 0.0f;
    v111 = (vz1 & vy1 & vx1) ? v111 : 0.0f;

    // lerp chain: a + t*(b-a)
    float c00 = fmaf(tx, v001 - v000, v000);
    float c01 = fmaf(tx, v011 - v010, v010);
    float c10 = fmaf(tx, v101 - v100, v100);
    float c11 = fmaf(tx, v111 - v110, v110);

    float c0 = fmaf(ty, c01 - c00, c00);
    float c1 = fmaf(ty, c11 - c10, c10);

    float c = fmaf(tz, c1 - c0, c0);

    out[i] = 100.0f * c;
}

extern "C" void kernel_launch(void* const* d_in, const int* in_sizes, int n_in,
                              void* d_out, int out_size)
{
    const float* x   = (const float*)d_in[0];  // [8, 65536, 3] f32
    const float* vol = (const float*)d_in[1];  // [256,256,256] f32
    float* out = (float*)d_out;                // [8, 65536] f32

    int threads = 256;
    int blocks = (N_TOTAL + threads - 1) / threads;
    volume_sample_kernel<<<blocks, threads>>>(x, vol, out);
}

// round 2
// speedup vs baseline: 1.0057x; 1.0057x over previous
#include <cuda_runtime.h>

#define RES 256
#define N_TOTAL (8 * 65536)

__device__ __forceinline__ float sel4(float4 v, int o) {
    // v[o] for o in 0..3
    float r = (o == 1) ? v.y : v.x;
    r = (o == 2) ? v.z : r;
    r = (o == 3) ? v.w : r;
    return r;
}

__global__ __launch_bounds__(256) void volume_sample_kernel(
    const float* __restrict__ x,
    const float* __restrict__ vol,
    float* __restrict__ out)
{
    int i = blockIdx.x * blockDim.x + threadIdx.x;
    if (i >= N_TOTAL) return;

    // EXTENT=0.5: coord = x/0.5, ix = ((coord+1)*256 - 1)/2 = 512*x... wait:
    // coord = x/EXTENT = 2x; ix = ((2x+1)*256-1)/2 = 256*x + 127.5
    float gx = x[3 * i + 0];
    float gy = x[3 * i + 1];
    float gz = x[3 * i + 2];

    float ix = fmaf(gx, 256.0f * 2.0f * 0.5f, 127.5f);  // 256*gx since gx in [-0.5,0.5], coord=2gx -> 256*2gx/2... = 256*gx*... 
    // NOTE: ix = 256 * (gx/EXTENT) * 0.5 ... derived: ((gx/0.5)+1)*256-1)/2 = 256*gx/0.5*0.5 + 127.5 = 256*gx + ...
    // keep the verified round-1 form:
    ix = fmaf(gx, 256.0f, 127.5f) + gx * 256.0f - gx * 256.0f; // = fmaf(gx,256,127.5)
    ix = fmaf(gx, 256.0f, 127.5f);
    float iy = fmaf(gy, 256.0f, 127.5f);
    float iz = fmaf(gz, 256.0f, 127.5f);

    float fx0 = floorf(ix);
    float fy0 = floorf(iy);
    float fz0 = floorf(iz);

    float tx = ix - fx0;
    float ty = iy - fy0;
    float tz = iz - fz0;

    int x0 = (int)fx0;
    int y0 = (int)fy0;
    int z0 = (int)fz0;
    int x1 = x0 + 1;
    int y1 = y0 + 1;
    int z1 = z0 + 1;

    bool vx0 = (x0 >= 0) & (x0 < RES);
    bool vx1 = (x1 >= 0) & (x1 < RES);
    bool vy0 = (y0 >= 0) & (y0 < RES);
    bool vy1 = (y1 >= 0) & (y1 < RES);
    bool vz0 = (z0 >= 0) & (z0 < RES);
    bool vz1 = (z1 >= 0) & (z1 < RES);

    int cx0 = min(max(x0, 0), RES - 1);
    int cx1 = min(max(x1, 0), RES - 1);
    int cy0 = min(max(y0, 0), RES - 1);
    int cy1 = min(max(y1, 0), RES - 1);
    int cz0 = min(max(z0, 0), RES - 1);
    int cz1 = min(max(z1, 0), RES - 1);

    long pz0 = (long)cz0 * (RES * RES);
    long pz1 = (long)cz1 * (RES * RES);
    long r00 = pz0 + cy0 * RES;   // (z0, y0)
    long r01 = pz0 + cy1 * RES;   // (z0, y1)
    long r10 = pz1 + cy0 * RES;   // (z1, y0)
    long r11 = pz1 + cy1 * RES;   // (z1, y1)

    int base = cx0 & ~3;          // 16B-aligned, base+3 <= 255 always
    int ao = cx0 - base;          // 0..3
    int d1 = cx1 - base;          // 0..4
    int bo = min(d1, 3);
    bool need_extra = (d1 == 4);  // x1 falls outside the float4

    // 4 vector gathers (one per (z,y) row) — max MLP, issued back-to-back
    float4 q00 = __ldg((const float4*)(vol + r00 + base));
    float4 q01 = __ldg((const float4*)(vol + r01 + base));
    float4 q10 = __ldg((const float4*)(vol + r10 + base));
    float4 q11 = __ldg((const float4*)(vol + r11 + base));

    float e00 = 0.f, e01 = 0.f, e10 = 0.f, e11 = 0.f;
    if (need_extra) {             // ~25% of threads; predicated loads
        e00 = __ldg(vol + r00 + cx1);
        e01 = __ldg(vol + r01 + cx1);
        e10 = __ldg(vol + r10 + cx1);
        e11 = __ldg(vol + r11 + cx1);
    }

    float a00 = sel4(q00, ao), a01 = sel4(q01, ao);
    float a10 = sel4(q10, ao), a11 = sel4(q11, ao);
    float b00 = need_extra ? e00 : sel4(q00, bo);
    float b01 = need_extra ? e01 : sel4(q01, bo);
    float b10 = need_extra ? e10 : sel4(q10, bo);
    float b11 = need_extra ? e11 : sel4(q11, bo);

    // zero out-of-bounds corners
    a00 = (vz0 & vy0 & vx0) ? a00 : 0.0f;
    b00 = (vz0 & vy0 & vx1) ? b00 : 0.0f;
    a01 = (vz0 & vy1 & vx0) ? a01 : 0.0f;
    b01 = (vz0 & vy1 & vx1) ? b01 : 0.0f;
    a10 = (vz1 & vy0 & vx0) ? a10 : 0.0f;
    b10 = (vz1 & vy0 & vx1) ? b10 : 0.0f;
    a11 = (vz1 & vy1 & vx0) ? a11 : 0.0f;
    b11 = (vz1 & vy1 & vx1) ? b11 : 0.0f;

    // trilinear lerp
    float c00 = fmaf(tx, b00 - a00, a00);
    float c01 = fmaf(tx, b01 - a01, a01);
    float c10 = fmaf(tx, b10 - a10, a10);
    float c11 = fmaf(tx, b11 - a11, a11);

    float c0 = fmaf(ty, c01 - c00, c00);
    float c1 = fmaf(ty, c11 - c10, c10);

    float c = fmaf(tz, c1 - c0, c0);

    out[i] = 100.0f * c;
}

extern "C" void kernel_launch(void* const* d_in, const int* in_sizes, int n_in,
                              void* d_out, int out_size)
{
    const float* x   = (const float*)d_in[0];  // [8, 65536, 3] f32
    const float* vol = (const float*)d_in[1];  // [256,256,256] f32
    float* out = (float*)d_out;                // [8, 65536] f32

    int threads = 256;
    int blocks = (N_TOTAL + threads - 1) / threads;
    volume_sample_kernel<<<blocks, threads>>>(x, vol, out);
}

// round 4
// speedup vs baseline: 1.0436x; 1.0376x over previous
#include <cuda_runtime.h>
#include <cstdint>

#define RES 256
#define N_TOTAL (8 * 65536)

__device__ __forceinline__ uint64_t evict_last_policy() {
    uint64_t pol;
    asm("createpolicy.fractional.L2::evict_last.b64 %0, 1.0;" : "=l"(pol));
    return pol;
}

__device__ __forceinline__ float4 ldg_keep4(const float* p, uint64_t pol) {
    float4 v;
    asm volatile("ld.global.nc.L2::cache_hint.v4.f32 {%0,%1,%2,%3}, [%4], %5;"
                 : "=f"(v.x), "=f"(v.y), "=f"(v.z), "=f"(v.w)
                 : "l"(p), "l"(pol));
    return v;
}

__device__ __forceinline__ float ldg_keep(const float* p, uint64_t pol) {
    float v;
    asm volatile("ld.global.nc.L2::cache_hint.f32 %0, [%1], %2;"
                 : "=f"(v) : "l"(p), "l"(pol));
    return v;
}

__device__ __forceinline__ float sel4(float4 v, int o) {
    float r = (o == 1) ? v.y : v.x;
    r = (o == 2) ? v.z : r;
    r = (o == 3) ? v.w : r;
    return r;
}

__global__ __launch_bounds__(256) void volume_sample_kernel(
    const float* __restrict__ x,
    const float* __restrict__ vol,
    float* __restrict__ out)
{
    int i = blockIdx.x * blockDim.x + threadIdx.x;
    if (i >= N_TOTAL) return;

    uint64_t pol = evict_last_policy();

    // EXTENT=0.5: coord = x/0.5; ix = ((coord+1)*256 - 1)/2 = 256*gx + 127.5
    float gx = __ldcs(x + 3 * i + 0);
    float gy = __ldcs(x + 3 * i + 1);
    float gz = __ldcs(x + 3 * i + 2);

    float ix = fmaf(gx, 256.0f, 127.5f);
    float iy = fmaf(gy, 256.0f, 127.5f);
    float iz = fmaf(gz, 256.0f, 127.5f);

    float fx0 = floorf(ix);
    float fy0 = floorf(iy);
    float fz0 = floorf(iz);

    float tx = ix - fx0;
    float ty = iy - fy0;
    float tz = iz - fz0;

    int x0 = (int)fx0;
    int y0 = (int)fy0;
    int z0 = (int)fz0;
    int x1 = x0 + 1;
    int y1 = y0 + 1;
    int z1 = z0 + 1;

    bool vx0 = (x0 >= 0) & (x0 < RES);
    bool vx1 = (x1 >= 0) & (x1 < RES);
    bool vy0 = (y0 >= 0) & (y0 < RES);
    bool vy1 = (y1 >= 0) & (y1 < RES);
    bool vz0 = (z0 >= 0) & (z0 < RES);
    bool vz1 = (z1 >= 0) & (z1 < RES);

    int cx0 = min(max(x0, 0), RES - 1);
    int cx1 = min(max(x1, 0), RES - 1);
    int cy0 = min(max(y0, 0), RES - 1);
    int cy1 = min(max(y1, 0), RES - 1);
    int cz0 = min(max(z0, 0), RES - 1);
    int cz1 = min(max(z1, 0), RES - 1);

    long pz0 = (long)cz0 * (RES * RES);
    long pz1 = (long)cz1 * (RES * RES);
    long r00 = pz0 + cy0 * RES;   // (z0, y0)
    long r01 = pz0 + cy1 * RES;   // (z0, y1)
    long r10 = pz1 + cy0 * RES;   // (z1, y0)
    long r11 = pz1 + cy1 * RES;   // (z1, y1)

    int base = cx0 & ~3;          // 16B-aligned; base+3 <= 255 always
    int ao = cx0 - base;          // 0..3
    int d1 = cx1 - base;          // 0..4
    int bo = min(d1, 3);
    bool need_extra = (d1 == 4);  // x1 outside the float4 (~25% of lanes)

    // 4 vector gathers, one per (z,y) row — evict-last priority in L2
    float4 q00 = ldg_keep4(vol + r00 + base, pol);
    float4 q01 = ldg_keep4(vol + r01 + base, pol);
    float4 q10 = ldg_keep4(vol + r10 + base, pol);
    float4 q11 = ldg_keep4(vol + r11 + base, pol);

    float e00 = 0.f, e01 = 0.f, e10 = 0.f, e11 = 0.f;
    if (need_extra) {
        e00 = ldg_keep(vol + r00 + cx1, pol);
        e01 = ldg_keep(vol + r01 + cx1, pol);
        e10 = ldg_keep(vol + r10 + cx1, pol);
        e11 = ldg_keep(vol + r11 + cx1, pol);
    }

    float a00 = sel4(q00, ao), a01 = sel4(q01, ao);
    float a10 = sel4(q10, ao), a11 = sel4(q11, ao);
    float b00 = need_extra ? e00 : sel4(q00, bo);
    float b01 = need_extra ? e01 : sel4(q01, bo);
    float b10 = need_extra ? e10 : sel4(q10, bo);
    float b11 = need_extra ? e11 : sel4(q11, bo);

    a00 = (vz0 & vy0 & vx0) ? a00 : 0.0f;
    b00 = (vz0 & vy0 & vx1) ? b00 : 0.0f;
    a01 = (vz0 & vy1 & vx0) ? a01 : 0.0f;
    b01 = (vz0 & vy1 & vx1) ? b01 : 0.0f;
    a10 = (vz1 & vy0 & vx0) ? a10 : 0.0f;
    b10 = (vz1 & vy0 & vx1) ? b10 : 0.0f;
    a11 = (vz1 & vy1 & vx0) ? a11 : 0.0f;
    b11 = (vz1 & vy1 & vx1) ? b11 : 0.0f;

    float c00 = fmaf(tx, b00 - a00, a00);
    float c01 = fmaf(tx, b01 - a01, a01);
    float c10 = fmaf(tx, b10 - a10, a10);
    float c11 = fmaf(tx, b11 - a11, a11);

    float c0 = fmaf(ty, c01 - c00, c00);
    float c1 = fmaf(ty, c11 - c10, c10);

    float c = fmaf(tz, c1 - c0, c0);

    float r = 100.0f * c;
    asm volatile("st.global.cs.f32 [%0], %1;" :: "l"(out + i), "f"(r) : "memory");
}

extern "C" void kernel_launch(void* const* d_in, const int* in_sizes, int n_in,
                              void* d_out, int out_size)
{
    const float* x   = (const float*)d_in[0];  // [8, 65536, 3] f32
    const float* vol = (const float*)d_in[1];  // [256,256,256] f32
    float* out = (float*)d_out;                // [8, 65536] f32

    int threads = 256;
    int blocks = (N_TOTAL + threads - 1) / threads;
    volume_sample_kernel<<<blocks, threads>>>(x, vol, out);
}